// round 7
// baseline (speedup 1.0000x reference)
#include <cuda_runtime.h>

#define B_DIM 8
#define H_DIM 8
#define P_DIM 4
#define PB 32
#define FEAT 64
#define EMB 32
#define HIN 96
#define GH 32
#define T_DIM 101770
#define TILE_T 128
#define NUM_TILES ((T_DIM + TILE_T - 1) / TILE_T)   // 796
#define ATT_STRIDE 100
#define GEN_STRIDE 36
#define GRID_MAIN 148                                // 1 block per SM

// buffer layout (floats)
#define OFF_ATT  0
#define OFF_GEN  (TILE_T * ATT_STRIDE)               // 12800
#define OFF_HMID (OFF_GEN + TILE_T * GEN_STRIDE)     // 17408
#define OFF_GB   (OFF_HMID + PB * GH)                // 18432
#define OFF_AB   (OFF_GB + TILE_T)                   // 18560
#define BUF_FLOATS (OFF_AB + TILE_T)                 // 18688 (74752B, 16B aligned)

// ---------------- device scratch ----------------
__device__ __align__(16) float g_hin[PB * HIN];
__device__ __align__(16) float g_hmid[H_DIM * PB * GH];
__device__ __align__(16) float g_gate[B_DIM * H_DIM];

// ---------------- helpers ----------------
static __device__ __forceinline__ unsigned long long ffma2(
    unsigned long long a, unsigned long long b, unsigned long long c) {
    unsigned long long d;
    asm("fma.rn.f32x2 %0, %1, %2, %3;" : "=l"(d) : "l"(a), "l"(b), "l"(c));
    return d;
}
static __device__ __forceinline__ float2 upk(unsigned long long a) {
    float2 f;
    asm("mov.b64 {%0, %1}, %2;" : "=f"(f.x), "=f"(f.y) : "l"(a));
    return f;
}
static __device__ __forceinline__ unsigned smem_u32(const void* p) {
    return (unsigned)__cvta_generic_to_shared(p);
}
#define CP16(dst, src) asm volatile("cp.async.cg.shared.global [%0], [%1], 16;" :: "r"(dst), "l"(src))
#define CP8(dst, src)  asm volatile("cp.async.ca.shared.global [%0], [%1], 8;"  :: "r"(dst), "l"(src))
#define CP_COMMIT()    asm volatile("cp.async.commit_group;")
#define CP_WAIT1()     asm volatile("cp.async.wait_group 1;")

// ---------------- merged setup (single block, 256 threads) ----------------
__global__ void k_setup(const float* __restrict__ x,
                        const float* __restrict__ fe_W1, const float* __restrict__ fe_b1,
                        const float* __restrict__ fe_W2, const float* __restrict__ fe_b2,
                        const float* __restrict__ embeds,
                        const float* __restrict__ gen_W1, const float* __restrict__ gen_b1,
                        const float* __restrict__ gate_W, const float* __restrict__ gate_b) {
    __shared__ float sh1[B_DIM * 128];      // 1024
    __shared__ float sfe[B_DIM * FEAT];     // 512
    __shared__ float shin[PB * HIN];        // 3072
    int tid = threadIdx.x;                  // 256

    // Phase A: h1 = relu(x @ fe_W1^T + fe_b1)
    for (int o = tid; o < B_DIM * 128; o += 256) {
        int b = o >> 7, j = o & 127;
        const float4* xr = (const float4*)(x + b * 784);
        const float4* wr = (const float4*)(fe_W1 + (size_t)j * 784);
        float s = 0.f;
#pragma unroll 4
        for (int i = 0; i < 196; i++) {
            float4 a = xr[i], w = wr[i];
            s += a.x * w.x + a.y * w.y + a.z * w.z + a.w * w.w;
        }
        sh1[o] = fmaxf(s + fe_b1[j], 0.f);
    }
    __syncthreads();

    // Phase B1: feats = h1 @ fe_W2^T + fe_b2
    for (int o = tid; o < B_DIM * FEAT; o += 256) {
        int b = o >> 6, f = o & 63;
        const float* w = fe_W2 + f * 128;
        const float* hh = sh1 + b * 128;
        float s = 0.f;
#pragma unroll 8
        for (int k = 0; k < 128; k++) s += hh[k] * w[k];
        sfe[o] = s + fe_b2[f];
    }
    __syncthreads();

    // Phase B2: gate softmax + hin assembly
    if (tid < B_DIM) {
        int b = tid;
        float l[H_DIM];
        float m = -1e30f;
        for (int h = 0; h < H_DIM; h++) {
            float s = gate_b[h];
            for (int f = 0; f < FEAT; f++) s += sfe[b * FEAT + f] * gate_W[h * FEAT + f];
            l[h] = s;
            m = fmaxf(m, s);
        }
        float sum = 0.f;
        for (int h = 0; h < H_DIM; h++) { l[h] = expf(l[h] - m); sum += l[h]; }
        float inv = 1.f / sum;
        for (int h = 0; h < H_DIM; h++) g_gate[b * H_DIM + h] = l[h] * inv;
    }
    for (int i = tid; i < PB * HIN; i += 256) {
        int pb = i / HIN, k = i % HIN;
        int p = pb >> 3, bb = pb & 7;
        float v = (k < FEAT) ? sfe[bb * FEAT + k] : embeds[p * EMB + (k - FEAT)];
        shin[i] = v;
        g_hin[i] = v;
    }
    __syncthreads();

    // Phase C: hmid = relu(hin @ gen_W1^T + gen_b1)
    for (int o = tid; o < H_DIM * PB * GH; o += 256) {
        int h = o >> 10, r = o & 1023, pb = r >> 5, j = r & 31;
        const float4* w = (const float4*)(gen_W1 + (size_t)(h * GH + j) * HIN);
        const float4* hv = (const float4*)(shin + pb * HIN);
        float s = 0.f;
#pragma unroll
        for (int i = 0; i < HIN / 4; i++) {
            float4 a = hv[i], ww = w[i];
            s += a.x * ww.x + a.y * ww.y + a.z * ww.z + a.w * ww.w;
        }
        g_hmid[(h * PB + pb) * GH + j] = fmaxf(s + gen_b1[h * GH + j], 0.f);
    }
}

// ---------------- staging one (tile,h) into a buffer via cp.async ----------------
static __device__ __forceinline__ void stage_iter(
    float* buf, int tile, int h, int tid,
    const float* __restrict__ attW, const float* __restrict__ attB,
    const float* __restrict__ genW2, const float* __restrict__ genB2) {
    const int t0 = tile * TILE_T;
    const int nrow = min(TILE_T, T_DIM - t0);
    const unsigned uAtt  = smem_u32(buf + OFF_ATT);
    const unsigned uGen  = smem_u32(buf + OFF_GEN);
    const unsigned uHmid = smem_u32(buf + OFF_HMID);
    const unsigned uGb   = smem_u32(buf + OFF_GB);
    const unsigned uAb   = smem_u32(buf + OFF_AB);
    const float4* srcA = (const float4*)(attW + (size_t)(h * T_DIM + t0) * HIN);
    const float4* srcG = (const float4*)(genW2 + (size_t)(h * T_DIM + t0) * GH);
    const float4* srcM = (const float4*)(g_hmid + h * PB * GH);

    if (nrow == TILE_T) {
#pragma unroll 4
        for (int it = 0; it < HIN / 4; ++it) {          // 24
            int i = tid + it * TILE_T;
            int r = i / (HIN / 4), c = i % (HIN / 4);
            CP16(uAtt + (unsigned)(r * ATT_STRIDE + c * 4) * 4u, srcA + i);
        }
#pragma unroll
        for (int it = 0; it < GH / 4; ++it) {           // 8
            int i = tid + it * TILE_T;
            int r = i >> 3, c = i & 7;
            CP16(uGen + (unsigned)(r * GEN_STRIDE + c * 4) * 4u, srcG + i);
        }
        CP16(uHmid + (unsigned)tid * 16u, srcM + tid);
        CP16(uHmid + (unsigned)(tid + 128) * 16u, srcM + tid + 128);
        if (tid < 64) {
            CP8(uGb + (unsigned)tid * 8u,
                (const char*)(genB2 + (size_t)h * T_DIM + t0) + (size_t)tid * 8);
        } else {
            int q = tid - 64;
            CP8(uAb + (unsigned)q * 8u,
                (const char*)(attB + (size_t)h * T_DIM + t0) + (size_t)q * 8);
        }
    } else {
        int nA = nrow * (HIN / 4);
#pragma unroll 4
        for (int it = 0; it < HIN / 4; ++it) {
            int i = tid + it * TILE_T;
            if (i < nA) {
                int r = i / (HIN / 4), c = i % (HIN / 4);
                CP16(uAtt + (unsigned)(r * ATT_STRIDE + c * 4) * 4u, srcA + i);
            }
        }
        int nG = nrow * (GH / 4);
#pragma unroll
        for (int it = 0; it < GH / 4; ++it) {
            int i = tid + it * TILE_T;
            if (i < nG) {
                int r = i >> 3, c = i & 7;
                CP16(uGen + (unsigned)(r * GEN_STRIDE + c * 4) * 4u, srcG + i);
            }
        }
        CP16(uHmid + (unsigned)tid * 16u, srcM + tid);
        CP16(uHmid + (unsigned)(tid + 128) * 16u, srcM + tid + 128);
        if (tid < 64) {
            if (tid * 2 < nrow)
                CP8(uGb + (unsigned)tid * 8u,
                    (const char*)(genB2 + (size_t)h * T_DIM + t0) + (size_t)tid * 8);
        } else {
            int q = tid - 64;
            if (q * 2 < nrow)
                CP8(uAb + (unsigned)q * 8u,
                    (const char*)(attB + (size_t)h * T_DIM + t0) + (size_t)q * 8);
        }
    }
}

// ---------------- main fused kernel --------------------------------------
// 128 threads = 32 t-lanes x 4 pb-groups; each thread: 4 t x 8 pb.
// Double-buffered cp.async pipeline over linearized (tile, h) iterations.
__global__ __launch_bounds__(128, 1) void k_main(
    const float* __restrict__ attW, const float* __restrict__ attB,
    const float* __restrict__ genW2, const float* __restrict__ genB2,
    float* __restrict__ out) {
    extern __shared__ float smem[];
    float* bufs[2] = { smem, smem + BUF_FLOATS };
    float* sHin  = smem + 2 * BUF_FLOATS;                // 3072
    float* sGate = sHin + PB * HIN;                      // 64

    const int tid = threadIdx.x;
    const int lane = tid & 31;
    const int wpb = tid >> 5;
    const int bid = blockIdx.x;

    for (int i = tid; i < PB * HIN; i += 128) sHin[i] = g_hin[i];
    if (tid < B_DIM * H_DIM) sGate[tid] = g_gate[tid];

    const int ntile = (NUM_TILES - bid + GRID_MAIN - 1) / GRID_MAIN;
    const int nit = ntile * H_DIM;

    // prefetch iteration 0
    stage_iter(bufs[0], bid, 0, tid, attW, attB, genW2, genB2);
    CP_COMMIT();

    float comb[4][8];

    for (int it = 0; it < nit; ++it) {
        const int cur = it & 1;
        const int h = it & 7;
        const int tile = bid + (it >> 3) * GRID_MAIN;

        // prefetch next iteration into the other buffer
        if (it + 1 < nit) {
            const int nit2 = it + 1;
            stage_iter(bufs[cur ^ 1], bid + (nit2 >> 3) * GRID_MAIN, nit2 & 7, tid,
                       attW, attB, genW2, genB2);
        }
        CP_COMMIT();
        CP_WAIT1();          // current buffer's group has landed
        __syncthreads();

        float* buf = bufs[cur];
        const float* sAtt  = buf + OFF_ATT;
        const float* sGen  = buf + OFF_GEN;
        const float* sHmid = buf + OFF_HMID;
        const float* sGb   = buf + OFF_GB;
        const float* sAb   = buf + OFF_AB;

        if (h == 0) {
#pragma unroll
            for (int jt = 0; jt < 4; ++jt)
#pragma unroll
                for (int j = 0; j < 8; ++j) comb[jt][j] = 0.f;
        }

        // ---------- gen GEMM ----------
        unsigned long long acc[4][8];
#pragma unroll
        for (int jt = 0; jt < 4; ++jt)
#pragma unroll
            for (int j = 0; j < 8; ++j) acc[jt][j] = 0ull;
#pragma unroll
        for (int k4 = 0; k4 < GH / 4; ++k4) {
            ulonglong2 w[4];
#pragma unroll
            for (int jt = 0; jt < 4; ++jt)
                w[jt] = *(const ulonglong2*)&sGen[(lane + 32 * jt) * GEN_STRIDE + k4 * 4];
#pragma unroll
            for (int j = 0; j < 8; ++j) {
                ulonglong2 hv = *(const ulonglong2*)&sHmid[(wpb * 8 + j) * GH + k4 * 4];
#pragma unroll
                for (int jt = 0; jt < 4; ++jt) {
                    acc[jt][j] = ffma2(hv.x, w[jt].x, acc[jt][j]);
                    acc[jt][j] = ffma2(hv.y, w[jt].y, acc[jt][j]);
                }
            }
        }
        float gb[4], ab[4];
#pragma unroll
        for (int jt = 0; jt < 4; ++jt) {
            gb[jt] = sGb[lane + 32 * jt];
            ab[jt] = sAb[lane + 32 * jt];
        }
        float gv[4][8];
#pragma unroll
        for (int jt = 0; jt < 4; ++jt)
#pragma unroll
            for (int j = 0; j < 8; ++j) {
                float2 f = upk(acc[jt][j]);
                gv[jt][j] = f.x + f.y + gb[jt];
                acc[jt][j] = 0ull;
            }

        // ---------- att GEMM ----------
#pragma unroll 4
        for (int k4 = 0; k4 < HIN / 4; ++k4) {
            ulonglong2 w[4];
#pragma unroll
            for (int jt = 0; jt < 4; ++jt)
                w[jt] = *(const ulonglong2*)&sAtt[(lane + 32 * jt) * ATT_STRIDE + k4 * 4];
#pragma unroll
            for (int j = 0; j < 8; ++j) {
                ulonglong2 hv = *(const ulonglong2*)&sHin[(wpb * 8 + j) * HIN + k4 * 4];
#pragma unroll
                for (int jt = 0; jt < 4; ++jt) {
                    acc[jt][j] = ffma2(hv.x, w[jt].x, acc[jt][j]);
                    acc[jt][j] = ffma2(hv.y, w[jt].y, acc[jt][j]);
                }
            }
        }

        // ---------- sigmoid + gated combine ----------
        float gt[8];
#pragma unroll
        for (int j = 0; j < 8; ++j) gt[j] = sGate[h * B_DIM + j];
#pragma unroll
        for (int jt = 0; jt < 4; ++jt)
#pragma unroll
            for (int j = 0; j < 8; ++j) {
                float2 f = upk(acc[jt][j]);
                float a = f.x + f.y + ab[jt];
                float imp = 1.0f / (1.0f + __expf(-a));
                comb[jt][j] = fmaf(gt[j] * gv[jt][j], imp, comb[jt][j]);
            }

        // ---------- store at last head ----------
        if (h == 7) {
            const int t0 = tile * TILE_T;
#pragma unroll
            for (int jt = 0; jt < 4; ++jt) {
                int t = t0 + lane + 32 * jt;
                if (t < T_DIM) {
#pragma unroll
                    for (int j = 0; j < 8; ++j)
                        out[(size_t)(j * P_DIM + wpb) * T_DIM + t] = comb[jt][j];
                }
            }
        }
        __syncthreads();     // compute done before this buffer is re-staged
    }
}

// ---------------- launch ----------------
extern "C" void kernel_launch(void* const* d_in, const int* in_sizes, int n_in,
                              void* d_out, int out_size) {
    const float* x      = (const float*)d_in[0];
    const float* fe_W1  = (const float*)d_in[1];
    const float* fe_b1  = (const float*)d_in[2];
    const float* fe_W2  = (const float*)d_in[3];
    const float* fe_b2  = (const float*)d_in[4];
    const float* embeds = (const float*)d_in[5];
    const float* gen_W1 = (const float*)d_in[6];
    const float* gen_b1 = (const float*)d_in[7];
    const float* gen_W2 = (const float*)d_in[8];
    const float* gen_b2 = (const float*)d_in[9];
    const float* att_W  = (const float*)d_in[10];
    const float* att_b  = (const float*)d_in[11];
    const float* gate_W = (const float*)d_in[12];
    const float* gate_b = (const float*)d_in[13];
    float* out = (float*)d_out;

    size_t smem = (size_t)(2 * BUF_FLOATS + PB * HIN + B_DIM * H_DIM) * sizeof(float);
    cudaFuncSetAttribute(k_main, cudaFuncAttributeMaxDynamicSharedMemorySize, (int)smem);

    k_setup<<<1, 256>>>(x, fe_W1, fe_b1, fe_W2, fe_b2, embeds,
                        gen_W1, gen_b1, gate_W, gate_b);
    k_main<<<GRID_MAIN, 128, smem>>>(att_W, att_b, gen_W2, gen_b2, out);
}